// round 2
// baseline (speedup 1.0000x reference)
#include <cuda_runtime.h>

#define BB   8192
#define JJ   16
#define NHID 128
#define NS4  (4*BB)                 // 32768 samples in branch phase
#define NRMAX (NS4*JJ)              // 524288 rows
#define EPSB 1e-5f

// ---------------- persistent scratch (device globals; no allocation) ----------------
__device__ float  g_H [NRMAX*NHID];   // pre-BN gconv output
__device__ float  g_X0[NRMAX*NHID];   // activation ping
__device__ float  g_X1[NRMAX*NHID];   // activation pong
__device__ float  g_Y1[NRMAX*NHID];   // joint-mixed input for next gemm
__device__ float  g_merged[BB*JJ*12];
__device__ float  g_att[15*JJ*JJ];    // 0:in 1:cat 2..9:res 10..14:out
__device__ double g_sum  [4*NHID];
__device__ double g_sumsq[4*NHID];
__device__ float  g_mu  [4*NHID];
__device__ float  g_istd[4*NHID];

// hardcoded H36M 16-joint mask (eye + edges), row i -> bitmask over j
__constant__ unsigned short c_mask[16] = {
 0x0093,0x0007,0x000E,0x000C,0x0031,0x0070,0x0060,0x0181,
 0x4B80,0x0700,0x0600,0x1900,0x3800,0x3000,0xC100,0xC000};

// ---------------- prep: masked softmax for all 15 attention matrices ----------------
__global__ void sg_prep(const float* __restrict__ e_in, const float* __restrict__ e_cat,
                        const float* __restrict__ e_res, const float* __restrict__ e_out)
{
    int t = threadIdx.x;
    for (int i = t; i < 4*NHID; i += 256) { g_sum[i] = 0.0; g_sumsq[i] = 0.0; }
    if (t < 240) {
        int slot = t >> 4, i = t & 15;
        const float* e;
        if (slot == 0)      e = e_in;
        else if (slot == 1) e = e_cat;
        else if (slot < 10) e = e_res + (slot-2)*256;
        else                e = e_out + (slot-10)*256;
        unsigned m = c_mask[i];
        float mx = -1e30f;
        for (int j = 0; j < 16; j++) if ((m>>j)&1) mx = fmaxf(mx, e[i*16+j]);
        float v[16]; float s = 0.f;
        for (int j = 0; j < 16; j++) {
            float x = ((m>>j)&1) ? expf(e[i*16+j]-mx) : 0.f;
            v[j] = x; s += x;
        }
        float inv = 1.f/s;
        for (int j = 0; j < 16; j++) g_att[slot*256 + i*16 + j] = v[j]*inv;
    }
}

// ---------------- small-K input gconv (K=2 branch-in, K=12 concat-in) ----------------
// mixes in input space, then h = y0@W0 + y1@W1 + b ; accumulates BN stats per set.
template<int KIN>
__global__ void sg_gconv_smallk(const float* __restrict__ x0, const float* __restrict__ x1,
                                const float* __restrict__ x2, const float* __restrict__ x3,
                                int fourway, const float* __restrict__ W,
                                const float* __restrict__ bias, int attSlot,
                                float* __restrict__ H)
{
    __shared__ float xs [8][16][KIN];
    __shared__ float y0s[8][16][KIN];
    __shared__ float y1s[8][16][KIN];
    __shared__ float Ws[2*KIN*NHID];
    __shared__ float attS[256];
    int t  = threadIdx.x;              // 128
    int s0 = blockIdx.x * 8;
    int set = blockIdx.x >> 10;        // 128 rows/block, 131072 rows/set

    for (int i = t; i < 2*KIN*NHID; i += 128) Ws[i] = W[i];
    for (int i = t; i < 256; i += 128) attS[i] = g_att[attSlot*256 + i];

    const int total = 8*16*KIN;
    for (int i = t; i < total; i += 128) {
        int s = i/(16*KIN); int rem = i - s*16*KIN; int j = rem/KIN; int k = rem - j*KIN;
        int gs = s0 + s;
        const float* xp; int loc;
        if (fourway) {
            int br = gs >> 13; loc = gs & (BB-1);
            xp = (br==0)?x0:(br==1)?x1:(br==2)?x2:x3;
        } else { xp = x0; loc = gs; }
        xs[s][j][k] = xp[(loc*16 + j)*KIN + k];
    }
    __syncthreads();
    for (int i = t; i < total; i += 128) {
        int s = i/(16*KIN); int rem = i - s*16*KIN; int ji = rem/KIN; int k = rem - ji*KIN;
        float a1 = 0.f;
        #pragma unroll
        for (int j = 0; j < 16; j++) a1 += attS[ji*16+j]*xs[s][j][k];
        a1 -= attS[ji*17]*xs[s][ji][k];
        y0s[s][ji][k] = attS[ji*17]*xs[s][ji][k];
        y1s[s][ji][k] = a1;
    }
    __syncthreads();
    int c = t;
    float w0[KIN], w1[KIN];
    #pragma unroll
    for (int k = 0; k < KIN; k++) { w0[k] = Ws[k*NHID+c]; w1[k] = Ws[(KIN+k)*NHID+c]; }
    float bb = bias[c];
    float bsum = 0.f, bsq = 0.f;
    for (int s = 0; s < 8; s++)
        for (int ji = 0; ji < 16; ji++) {
            float h = bb;
            #pragma unroll
            for (int k = 0; k < KIN; k++) h += y0s[s][ji][k]*w0[k] + y1s[s][ji][k]*w1[k];
            H[((s0+s)*16 + ji)*NHID + c] = h;
            bsum += h; bsq += h*h;
        }
    atomicAdd(&g_sum  [set*NHID + c], (double)bsum);
    atomicAdd(&g_sumsq[set*NHID + c], (double)bsq);
}

// ---------------- BN stat finalize (one block per set) ----------------
__global__ void sg_bn_finalize(float invN)
{
    int idx = blockIdx.x*NHID + threadIdx.x;
    double s = g_sum[idx], q = g_sumsq[idx];
    float mu  = (float)(s*(double)invN);
    float var = (float)(q*(double)invN) - mu*mu;
    g_mu[idx] = mu; g_istd[idx] = rsqrtf(var + EPSB);
    g_sum[idx] = 0.0; g_sumsq[idx] = 0.0;
}

// ---------------- BN apply + ReLU (+residual) + joint mix for next stage --------------
__global__ void sg_bn_mix(const float* __restrict__ H, const float* __restrict__ R,
                          float* __restrict__ Xout, float* __restrict__ Y1out,
                          const float* __restrict__ gma, const float* __restrict__ bta,
                          int attSlot, int makeY1)
{
    __shared__ float xn[4*16*128];     // 4 samples
    __shared__ float attS[256];
    __shared__ float muS[128], isS[128], gS[128], bS[128];
    int t = threadIdx.x;               // 256
    int set = blockIdx.x >> 11;        // 64 rows/block, 131072 rows/set
    if (t < 128) {
        muS[t] = g_mu[set*NHID+t]; isS[t] = g_istd[set*NHID+t];
        gS[t]  = gma[t];           bS[t]  = bta[t];
    }
    attS[t] = g_att[attSlot*256 + t];
    __syncthreads();
    long base = (long)blockIdx.x * 8192;
    for (int i = t; i < 8192; i += 256) {
        int c = i & 127;
        float v = H[base + i];
        v = fmaxf((v - muS[c])*isS[c]*gS[c] + bS[c], 0.f);
        if (R) v += R[base + i];
        xn[i] = v;
        Xout[base + i] = v;
    }
    __syncthreads();
    if (makeY1) {
        for (int i = t; i < 8192; i += 256) {
            int c = i & 127; int ji = (i >> 7) & 15; int s = i >> 11;
            const float* xr = xn + s*2048;
            float a = 0.f;
            #pragma unroll
            for (int j = 0; j < 16; j++) a += attS[ji*16+j]*xr[j*128 + c];
            a -= attS[ji*17]*xr[ji*128 + c];
            Y1out[base + i] = a;
        }
    }
}

// ---------------- main gemm: out = (d_i * X)@W0 + Y1@W1 + b, K=256 ----------------
#define GEMM_SMEM_FLOATS (256*128 + 2*8*132 + 256)
#define GEMM_SMEM_BYTES  (GEMM_SMEM_FLOATS*4)

__global__ __launch_bounds__(256) void sg_gemm128(
    const float* __restrict__ X, const float* __restrict__ Y1,
    const float* __restrict__ W, const float* __restrict__ bias,
    int attSlot, float* __restrict__ H)
{
    extern __shared__ float sm[];
    float* Ws   = sm;                  // [256][128]
    float* As   = sm + 256*128;        // 2 buffers of [8][132]
    float* sSum = As + 2*8*132;        // [128]
    float* sSq  = sSum + 128;          // [128]
    __shared__ float dS[16];
    __shared__ float bS[128];

    int tid = threadIdx.x;
    int tx = tid & 15, ty = tid >> 4;
    int blockRow0 = blockIdx.x * 128;
    int set = blockIdx.x >> 10;

    {   // whole weight matrix resident in smem
        const float4* W4 = (const float4*)W;
        float4* Ws4 = (float4*)Ws;
        #pragma unroll
        for (int i = 0; i < 32; i++) Ws4[tid + i*256] = W4[tid + i*256];
    }
    if (tid < 16)  dS[tid] = g_att[attSlot*256 + tid*17];
    if (tid < 128) { bS[tid] = bias[tid]; sSum[tid] = 0.f; sSq[tid] = 0.f; }
    __syncthreads();

    int r = tid >> 1, half = tid & 1;
    const float dsc = dS[r & 15];
    long rowBase = (long)(blockRow0 + r) * 128;

    float acc[8][8];
    #pragma unroll
    for (int i = 0; i < 8; i++)
        #pragma unroll
        for (int j = 0; j < 8; j++) acc[i][j] = 0.f;

    // tile 0
    {
        int k0 = half*4;
        float4 v = *(const float4*)(X + rowBase + k0);
        v.x *= dsc; v.y *= dsc; v.z *= dsc; v.w *= dsc;
        As[(k0+0)*132+r]=v.x; As[(k0+1)*132+r]=v.y; As[(k0+2)*132+r]=v.z; As[(k0+3)*132+r]=v.w;
    }
    __syncthreads();

    for (int tt = 0; tt < 32; tt++) {
        float4 nx;
        if (tt < 31) {
            int k0 = (tt+1)*8 + half*4;
            if (tt+1 < 16) {
                nx = *(const float4*)(X + rowBase + k0);
                nx.x*=dsc; nx.y*=dsc; nx.z*=dsc; nx.w*=dsc;
            } else {
                nx = *(const float4*)(Y1 + rowBase + (k0-128));
            }
        }
        const float* a  = As + (tt & 1)*1056;
        const float* wB = Ws + tt*8*128;
        #pragma unroll
        for (int kk = 0; kk < 8; kk++) {
            const float4* a4 = (const float4*)(a + kk*132 + ty*8);
            const float4* b4 = (const float4*)(wB + kk*128 + tx*8);
            float4 p = a4[0], q = a4[1];
            float4 u = b4[0], w = b4[1];
            float av[8] = {p.x,p.y,p.z,p.w,q.x,q.y,q.z,q.w};
            float bv[8] = {u.x,u.y,u.z,u.w,w.x,w.y,w.z,w.w};
            #pragma unroll
            for (int i = 0; i < 8; i++)
                #pragma unroll
                for (int j = 0; j < 8; j++) acc[i][j] += av[i]*bv[j];
        }
        if (tt < 31) {
            float* an = As + ((tt+1)&1)*1056;
            int kk = half*4;
            an[(kk+0)*132+r]=nx.x; an[(kk+1)*132+r]=nx.y; an[(kk+2)*132+r]=nx.z; an[(kk+3)*132+r]=nx.w;
            __syncthreads();
        }
    }

    // epilogue: bias, store H, per-channel stats
    int c0 = tx*8, r0 = ty*8;
    float cs[8], cq[8];
    #pragma unroll
    for (int j = 0; j < 8; j++) { cs[j] = 0.f; cq[j] = 0.f; }
    #pragma unroll
    for (int i = 0; i < 8; i++) {
        float o[8];
        #pragma unroll
        for (int j = 0; j < 8; j++) {
            float v = acc[i][j] + bS[c0+j];
            o[j] = v; cs[j] += v; cq[j] += v*v;
        }
        long row = (long)(blockRow0 + r0 + i);
        float4* Hp = (float4*)(H + row*128 + c0);
        Hp[0] = make_float4(o[0],o[1],o[2],o[3]);
        Hp[1] = make_float4(o[4],o[5],o[6],o[7]);
    }
    #pragma unroll
    for (int j = 0; j < 8; j++) { atomicAdd(&sSum[c0+j], cs[j]); atomicAdd(&sSq[c0+j], cq[j]); }
    __syncthreads();
    if (tid < 128) {
        atomicAdd(&g_sum  [set*NHID + tid], (double)sSum[tid]);
        atomicAdd(&g_sumsq[set*NHID + tid], (double)sSq[tid]);
    }
}

// ---------------- output semgconv (128 -> 3), per-branch weights/attention ------------
__global__ void sg_gconv_out(const float* __restrict__ X, const float* __restrict__ Wout,
                             const float* __restrict__ bout, int finalMode,
                             float* __restrict__ outp, float* __restrict__ merged)
{
    __shared__ float xs[4*16*129];
    __shared__ float Wl[768];
    __shared__ float attL[256];
    __shared__ float h1s[4][16][3];
    __shared__ float bL[3];
    int t  = threadIdx.x;              // 128
    int s0 = blockIdx.x * 4;
    int branch = finalMode ? 4 : (s0 >> 13);

    for (int i = t; i < 768; i += 128) Wl[i] = Wout[branch*768 + i];
    for (int i = t; i < 256; i += 128) attL[i] = g_att[(10+branch)*256 + i];
    if (t < 3) bL[t] = bout[branch*3 + t];
    for (int i = t; i < 4*16*128; i += 128) {
        int s = i >> 11, rem = i & 2047, j = rem >> 7, k = rem & 127;
        xs[(s*16+j)*129 + k] = X[((long)(s0+s)*16 + j)*128 + k];
    }
    __syncthreads();

    int si = t >> 4, ji = t & 15;
    float h0[3] = {0.f,0.f,0.f};
    if (t < 64) {
        float h1[3] = {0.f,0.f,0.f};
        const float* xr = xs + (si*16 + ji)*129;
        for (int k = 0; k < 128; k++) {
            float x = xr[k];
            h0[0] += x*Wl[k*3+0]; h0[1] += x*Wl[k*3+1]; h0[2] += x*Wl[k*3+2];
            h1[0] += x*Wl[384+k*3+0]; h1[1] += x*Wl[384+k*3+1]; h1[2] += x*Wl[384+k*3+2];
        }
        h1s[si][ji][0]=h1[0]; h1s[si][ji][1]=h1[1]; h1s[si][ji][2]=h1[2];
    }
    __syncthreads();
    if (t < 64) {
        float dd = attL[ji*17];
        float o[3];
        #pragma unroll
        for (int c = 0; c < 3; c++) o[c] = dd*h0[c] + bL[c];
        #pragma unroll
        for (int j = 0; j < 16; j++) {
            if (j == ji) continue;
            float a = attL[ji*16 + j];
            o[0] += a*h1s[si][j][0]; o[1] += a*h1s[si][j][1]; o[2] += a*h1s[si][j][2];
        }
        if (finalMode) {
            long row = ((long)(s0+si)*16 + ji)*3;
            outp[row+0]=o[0]; outp[row+1]=o[1]; outp[row+2]=o[2];
        } else {
            int loc = (s0+si) & (BB-1);
            long ob = (long)(1+branch)*BB*48 + ((long)loc*16 + ji)*3;
            outp[ob+0]=o[0]; outp[ob+1]=o[1]; outp[ob+2]=o[2];
            long mb = ((long)loc*16 + ji)*12 + branch*3;
            merged[mb+0]=o[0]; merged[mb+1]=o[1]; merged[mb+2]=o[2];
        }
    }
}

// ---------------- host orchestration ----------------
extern "C" void kernel_launch(void* const* d_in, const int* in_sizes, int n_in,
                              void* d_out, int out_size)
{
    const float* x1       = (const float*)d_in[0];
    const float* x2       = (const float*)d_in[1];
    const float* x3       = (const float*)d_in[2];
    const float* x4       = (const float*)d_in[3];
    const float* W_in     = (const float*)d_in[4];
    const float* b_in     = (const float*)d_in[5];
    const float* e_in     = (const float*)d_in[6];
    const float* g_in     = (const float*)d_in[7];
    const float* beta_in  = (const float*)d_in[8];
    const float* W_cat    = (const float*)d_in[9];
    const float* b_cat    = (const float*)d_in[10];
    const float* e_cat    = (const float*)d_in[11];
    const float* g_cat    = (const float*)d_in[12];
    const float* beta_cat = (const float*)d_in[13];
    const float* W_res    = (const float*)d_in[14];
    const float* b_res    = (const float*)d_in[15];
    const float* e_res    = (const float*)d_in[16];
    const float* g_res    = (const float*)d_in[17];
    const float* beta_res = (const float*)d_in[18];
    const float* W_out    = (const float*)d_in[19];
    const float* b_out    = (const float*)d_in[20];
    const float* e_out    = (const float*)d_in[21];
    float* out = (float*)d_out;

    float *Hb, *X0b, *X1b, *Y1b, *Mb;
    cudaGetSymbolAddress((void**)&Hb,  g_H);
    cudaGetSymbolAddress((void**)&X0b, g_X0);
    cudaGetSymbolAddress((void**)&X1b, g_X1);
    cudaGetSymbolAddress((void**)&Y1b, g_Y1);
    cudaGetSymbolAddress((void**)&Mb,  g_merged);

    cudaFuncSetAttribute(sg_gemm128, cudaFuncAttributeMaxDynamicSharedMemorySize, GEMM_SMEM_BYTES);

    sg_prep<<<1,256>>>(e_in, e_cat, e_res, e_out);

    const float invN = 1.f / (float)(BB*JJ);   // per-branch BN count == 131072 in both phases

    // ===== phase 1: 4 branches batched (32768 samples, 4 BN-stat sets) =====
    {
        int nS = NS4, nRows = nS*JJ, nSets = 4;
        sg_gconv_smallk<2><<<nS/8,128>>>(x1,x2,x3,x4, 1, W_in, b_in, 0, Hb);
        sg_bn_finalize<<<nSets,128>>>(invN);
        sg_bn_mix<<<nRows/64,256>>>(Hb, nullptr, X0b, Y1b, g_in, beta_in, 2, 1);
        for (int s = 0; s < 8; s++) {
            const float* Xin = (s & 1) ? X1b : X0b;
            sg_gemm128<<<nRows/128,256,GEMM_SMEM_BYTES>>>(Xin, Y1b, W_res + s*2*128*128,
                                                          b_res + s*128, 2+s, Hb);
            sg_bn_finalize<<<nSets,128>>>(invN);
            float* Xo       = (s & 1) ? X0b : X1b;
            const float* Rb = (s & 1) ? X0b : nullptr;
            int nextAtt = (s < 7) ? (3+s) : 0;
            sg_bn_mix<<<nRows/64,256>>>(Hb, Rb, Xo, Y1b, g_res + s*128, beta_res + s*128,
                                        nextAtt, (s < 7) ? 1 : 0);
        }
        sg_gconv_out<<<nS/4,128>>>(X0b, W_out, b_out, 0, out, Mb);   // out1..out4 + merged
    }

    // ===== phase 2: concat branch (8192 samples, 1 BN-stat set) =====
    {
        int nS = BB, nRows = nS*JJ, nSets = 1;
        sg_gconv_smallk<12><<<nS/8,128>>>(Mb, nullptr, nullptr, nullptr, 0, W_cat, b_cat, 1, Hb);
        sg_bn_finalize<<<nSets,128>>>(invN);
        sg_bn_mix<<<nRows/64,256>>>(Hb, nullptr, X0b, Y1b, g_cat, beta_cat, 2, 1);
        for (int s = 0; s < 8; s++) {
            const float* Xin = (s & 1) ? X1b : X0b;
            sg_gemm128<<<nRows/128,256,GEMM_SMEM_BYTES>>>(Xin, Y1b, W_res + s*2*128*128,
                                                          b_res + s*128, 2+s, Hb);
            sg_bn_finalize<<<nSets,128>>>(invN);
            float* Xo       = (s & 1) ? X0b : X1b;
            const float* Rb = (s & 1) ? X0b : nullptr;
            int nextAtt = (s < 7) ? (3+s) : 0;
            sg_bn_mix<<<nRows/64,256>>>(Hb, Rb, Xo, Y1b, g_res + s*128, beta_res + s*128,
                                        nextAtt, (s < 7) ? 1 : 0);
        }
        sg_gconv_out<<<nS/4,128>>>(X0b, W_out, b_out, 1, out, nullptr); // out_final at offset 0
    }
}

// round 4
// speedup vs baseline: 1.4462x; 1.4462x over previous
#include <cuda_runtime.h>
#include <cuda_bf16.h>
#include <cstdint>

#define BB   8192
#define JJ   16
#define NHID 128
#define NS4  (4*BB)
#define NRMAX (NS4*JJ)              // 524288 rows
#define EPSB 1e-5f
#define CSTRIDE 260
#define MIX_SMEM (128*CSTRIDE*4)

// ---------------- persistent scratch ----------------
__device__ float         g_H  [NRMAX*NHID];    // pre-BN gconv output (fp32)
__device__ __nv_bfloat16 g_Xh0[NRMAX*NHID];
__device__ __nv_bfloat16 g_Xl0[NRMAX*NHID];
__device__ __nv_bfloat16 g_Xh1[NRMAX*NHID];
__device__ __nv_bfloat16 g_Xl1[NRMAX*NHID];
__device__ __nv_bfloat16 g_Wbf[8*2*256*128];   // [stage][hi/lo][n=256][k=128]
__device__ float  g_merged[BB*JJ*12];
__device__ float  g_att[15*JJ*JJ];
__device__ double g_sum  [4*NHID];
__device__ double g_sumsq[4*NHID];
__device__ float  g_mu  [4*NHID];
__device__ float  g_istd[4*NHID];

__constant__ unsigned short c_mask[16] = {
 0x0093,0x0007,0x000E,0x000C,0x0031,0x0070,0x0060,0x0181,
 0x4B80,0x0700,0x0600,0x1900,0x3800,0x3000,0xC100,0xC000};

// ---------------- bf16 mma.sync (sm_80+ PTX; compiles for compute_103) ----------------
__device__ __forceinline__ void mma16816(float* c, const uint32_t* a, const uint32_t* b) {
    asm volatile("mma.sync.aligned.m16n8k16.row.col.f32.bf16.bf16.f32 "
        "{%0,%1,%2,%3}, {%4,%5,%6,%7}, {%8,%9}, {%0,%1,%2,%3};"
        : "+f"(c[0]), "+f"(c[1]), "+f"(c[2]), "+f"(c[3])
        : "r"(a[0]), "r"(a[1]), "r"(a[2]), "r"(a[3]), "r"(b[0]), "r"(b[1]));
}

// ---------------- prep: masked softmax for all 15 attention matrices ----------------
__global__ void sg_prep(const float* __restrict__ e_in, const float* __restrict__ e_cat,
                        const float* __restrict__ e_res, const float* __restrict__ e_out)
{
    int t = threadIdx.x;
    for (int i = t; i < 4*NHID; i += 256) { g_sum[i] = 0.0; g_sumsq[i] = 0.0; }
    if (t < 240) {
        int slot = t >> 4, i = t & 15;
        const float* e;
        if (slot == 0)      e = e_in;
        else if (slot == 1) e = e_cat;
        else if (slot < 10) e = e_res + (slot-2)*256;
        else                e = e_out + (slot-10)*256;
        unsigned m = c_mask[i];
        float mx = -1e30f;
        for (int j = 0; j < 16; j++) if ((m>>j)&1) mx = fmaxf(mx, e[i*16+j]);
        float v[16]; float s = 0.f;
        for (int j = 0; j < 16; j++) {
            float x = ((m>>j)&1) ? expf(e[i*16+j]-mx) : 0.f;
            v[j] = x; s += x;
        }
        float inv = 1.f/s;
        for (int j = 0; j < 16; j++) g_att[slot*256 + i*16 + j] = v[j]*inv;
    }
}

// ---------------- weight bf16 hi/lo split: g_Wbf[stage][hi/lo][n][k] ----------------
__global__ void sg_wprep(const float* __restrict__ W_res)
{
    int idx = blockIdx.x*256 + threadIdx.x;     // < 262144
    int s = idx >> 15;
    int part = (idx >> 14) & 1;
    int k = (idx >> 7) & 127;
    int c = idx & 127;
    float w = W_res[(((s*2 + part)*128) + k)*128 + c];
    __nv_bfloat16 hi = __float2bfloat16(w);
    __nv_bfloat16 lo = __float2bfloat16(w - __bfloat162float(hi));
    int n = part*128 + c;
    g_Wbf[((long)(s*2+0)*256 + n)*128 + k] = hi;
    g_Wbf[((long)(s*2+1)*256 + n)*128 + k] = lo;
}

// ---------------- small-K input gconv (K=2 / K=12), input-space mixing ----------------
template<int KIN>
__global__ void sg_gconv_smallk(const float* __restrict__ x0, const float* __restrict__ x1,
                                const float* __restrict__ x2, const float* __restrict__ x3,
                                int fourway, const float* __restrict__ W,
                                const float* __restrict__ bias, int attSlot,
                                float* __restrict__ H)
{
    __shared__ float xs [8][16][KIN];
    __shared__ float y0s[8][16][KIN];
    __shared__ float y1s[8][16][KIN];
    __shared__ float Ws[2*KIN*NHID];
    __shared__ float attS[256];
    int t  = threadIdx.x;              // 128
    int s0 = blockIdx.x * 8;
    int set = blockIdx.x >> 10;

    for (int i = t; i < 2*KIN*NHID; i += 128) Ws[i] = W[i];
    for (int i = t; i < 256; i += 128) attS[i] = g_att[attSlot*256 + i];

    const int total = 8*16*KIN;
    for (int i = t; i < total; i += 128) {
        int s = i/(16*KIN); int rem = i - s*16*KIN; int j = rem/KIN; int k = rem - j*KIN;
        int gs = s0 + s;
        const float* xp; int loc;
        if (fourway) {
            int br = gs >> 13; loc = gs & (BB-1);
            xp = (br==0)?x0:(br==1)?x1:(br==2)?x2:x3;
        } else { xp = x0; loc = gs; }
        xs[s][j][k] = xp[(loc*16 + j)*KIN + k];
    }
    __syncthreads();
    for (int i = t; i < total; i += 128) {
        int s = i/(16*KIN); int rem = i - s*16*KIN; int ji = rem/KIN; int k = rem - ji*KIN;
        float a1 = 0.f;
        #pragma unroll
        for (int j = 0; j < 16; j++) a1 += attS[ji*16+j]*xs[s][j][k];
        a1 -= attS[ji*17]*xs[s][ji][k];
        y0s[s][ji][k] = attS[ji*17]*xs[s][ji][k];
        y1s[s][ji][k] = a1;
    }
    __syncthreads();
    int c = t;
    float w0[KIN], w1[KIN];
    #pragma unroll
    for (int k = 0; k < KIN; k++) { w0[k] = Ws[k*NHID+c]; w1[k] = Ws[(KIN+k)*NHID+c]; }
    float bb = bias[c];
    float bsum = 0.f, bsq = 0.f;
    for (int s = 0; s < 8; s++)
        for (int ji = 0; ji < 16; ji++) {
            float h = bb;
            #pragma unroll
            for (int k = 0; k < KIN; k++) h += y0s[s][ji][k]*w0[k] + y1s[s][ji][k]*w1[k];
            H[((long)(s0+s)*16 + ji)*NHID + c] = h;
            bsum += h; bsq += h*h;
        }
    atomicAdd(&g_sum  [set*NHID + c], (double)bsum);
    atomicAdd(&g_sumsq[set*NHID + c], (double)bsq);
}

// ---------------- BN stat finalize ----------------
__global__ void sg_bn_finalize(float invN)
{
    int idx = blockIdx.x*NHID + threadIdx.x;
    double s = g_sum[idx], q = g_sumsq[idx];
    float mu  = (float)(s*(double)invN);
    float var = (float)(q*(double)invN) - mu*mu;
    g_mu[idx] = mu; g_istd[idx] = rsqrtf(var + EPSB);
    g_sum[idx] = 0.0; g_sumsq[idx] = 0.0;
}

// ---------------- convert: BN + ReLU (+residual), write bf16 hi/lo split -------------
__global__ void sg_convert(const float* __restrict__ H,
                           const __nv_bfloat16* __restrict__ Rh, const __nv_bfloat16* __restrict__ Rl,
                           __nv_bfloat16* __restrict__ Xh, __nv_bfloat16* __restrict__ Xl,
                           const float* __restrict__ gma, const float* __restrict__ bta)
{
    int t = threadIdx.x;               // 256
    long base = (long)blockIdx.x * 8192;   // 64 rows
    int set = blockIdx.x >> 11;
    int c0 = (t*4) & 127;
    float a[4], b[4];
    #pragma unroll
    for (int k = 0; k < 4; k++) {
        float mu = g_mu[set*NHID + c0 + k], is = g_istd[set*NHID + c0 + k];
        float gg = gma[c0+k], bb = bta[c0+k];
        a[k] = is*gg; b[k] = bb - mu*is*gg;
    }
    for (int i = t*4; i < 8192; i += 1024) {
        float4 h = *(const float4*)(H + base + i);
        float v[4];
        v[0] = fmaxf(fmaf(h.x, a[0], b[0]), 0.f);
        v[1] = fmaxf(fmaf(h.y, a[1], b[1]), 0.f);
        v[2] = fmaxf(fmaf(h.z, a[2], b[2]), 0.f);
        v[3] = fmaxf(fmaf(h.w, a[3], b[3]), 0.f);
        if (Rh) {
            __nv_bfloat162 rh0 = *(const __nv_bfloat162*)(Rh + base + i);
            __nv_bfloat162 rh1 = *(const __nv_bfloat162*)(Rh + base + i + 2);
            __nv_bfloat162 rl0 = *(const __nv_bfloat162*)(Rl + base + i);
            __nv_bfloat162 rl1 = *(const __nv_bfloat162*)(Rl + base + i + 2);
            v[0] += __bfloat162float(rh0.x) + __bfloat162float(rl0.x);
            v[1] += __bfloat162float(rh0.y) + __bfloat162float(rl0.y);
            v[2] += __bfloat162float(rh1.x) + __bfloat162float(rl1.x);
            v[3] += __bfloat162float(rh1.y) + __bfloat162float(rl1.y);
        }
        __nv_bfloat16 hh[4], ll[4];
        #pragma unroll
        for (int k = 0; k < 4; k++) {
            hh[k] = __float2bfloat16(v[k]);
            ll[k] = __float2bfloat16(v[k] - __bfloat162float(hh[k]));
        }
        __nv_bfloat162 p0, p1, q0, q1;
        p0.x = hh[0]; p0.y = hh[1]; p1.x = hh[2]; p1.y = hh[3];
        q0.x = ll[0]; q0.y = ll[1]; q1.x = ll[2]; q1.y = ll[3];
        *(__nv_bfloat162*)(Xh + base + i)     = p0;
        *(__nv_bfloat162*)(Xh + base + i + 2) = p1;
        *(__nv_bfloat162*)(Xl + base + i)     = q0;
        *(__nv_bfloat162*)(Xl + base + i + 2) = q1;
    }
}

// ---------------- HMMA gemm: C[128x256] = X @ [W0|W1]^T, bf16x3, fp32 acc -----------
// Epilogue: H = D*C0 + M1*C1 + bias (output-space joint mix) + BN stats.
__global__ __launch_bounds__(512) void sg_gemm_mma(
    const __nv_bfloat16* __restrict__ Xh, const __nv_bfloat16* __restrict__ Xl,
    const __nv_bfloat16* __restrict__ Wbf, const float* __restrict__ bias,
    int attSlot, float* __restrict__ H)
{
    extern __shared__ float Cs[];      // [128][CSTRIDE]
    __shared__ float att2[256];
    __shared__ float dS[16];
    __shared__ float bS[128];
    __shared__ float sSum[128], sSq[128];

    int tid = threadIdx.x, wid = tid >> 5, lane = tid & 31;
    int row0 = blockIdx.x * 128;
    int set  = blockIdx.x >> 10;
    int g = lane >> 2, tg = lane & 3;
    int wm = wid >> 2, wn = wid & 3;   // 4x4 warp grid, tile 32(M) x 64(N)

    if (tid < 128) { bS[tid] = bias[tid]; sSum[tid] = 0.f; sSq[tid] = 0.f; }
    if (tid < 256) {
        float av = g_att[attSlot*256 + tid];
        int i = tid >> 4, j = tid & 15;
        att2[tid] = (i == j) ? 0.f : av;
        if (i == j) dS[i] = av;
    }

    // row pointers for A fragments (2 m-tiles x {g, g+8})
    const __nv_bfloat16* rA[4];
    const __nv_bfloat16* rAl[4];
    #pragma unroll
    for (int mt = 0; mt < 2; mt++) {
        long r1 = (long)(row0 + wm*32 + mt*16 + g) * 128;
        rA [mt*2+0] = Xh + r1;        rA [mt*2+1] = Xh + r1 + 8*128;
        rAl[mt*2+0] = Xl + r1;        rAl[mt*2+1] = Xl + r1 + 8*128;
    }
    const __nv_bfloat16* Wh = Wbf;
    const __nv_bfloat16* Wl = Wbf + 256*128;

    float acc[2][8][4];
    #pragma unroll
    for (int mt = 0; mt < 2; mt++)
        #pragma unroll
        for (int nt = 0; nt < 8; nt++)
            #pragma unroll
            for (int q = 0; q < 4; q++) acc[mt][nt][q] = 0.f;

    #pragma unroll
    for (int ks = 0; ks < 8; ks++) {
        int k0 = ks*16;
        uint32_t ah[2][4], al[2][4];
        #pragma unroll
        for (int mt = 0; mt < 2; mt++) {
            ah[mt][0] = *(const uint32_t*)(rA [mt*2+0] + k0 + tg*2);
            ah[mt][1] = *(const uint32_t*)(rA [mt*2+1] + k0 + tg*2);
            ah[mt][2] = *(const uint32_t*)(rA [mt*2+0] + k0 + 8 + tg*2);
            ah[mt][3] = *(const uint32_t*)(rA [mt*2+1] + k0 + 8 + tg*2);
            al[mt][0] = *(const uint32_t*)(rAl[mt*2+0] + k0 + tg*2);
            al[mt][1] = *(const uint32_t*)(rAl[mt*2+1] + k0 + tg*2);
            al[mt][2] = *(const uint32_t*)(rAl[mt*2+0] + k0 + 8 + tg*2);
            al[mt][3] = *(const uint32_t*)(rAl[mt*2+1] + k0 + 8 + tg*2);
        }
        #pragma unroll
        for (int nt = 0; nt < 8; nt++) {
            int n = wn*64 + nt*8 + g;
            uint32_t bh[2], bl[2];
            bh[0] = *(const uint32_t*)(Wh + (long)n*128 + k0 + tg*2);
            bh[1] = *(const uint32_t*)(Wh + (long)n*128 + k0 + 8 + tg*2);
            bl[0] = *(const uint32_t*)(Wl + (long)n*128 + k0 + tg*2);
            bl[1] = *(const uint32_t*)(Wl + (long)n*128 + k0 + 8 + tg*2);
            #pragma unroll
            for (int mt = 0; mt < 2; mt++) {
                mma16816(acc[mt][nt], ah[mt], bh);
                mma16816(acc[mt][nt], al[mt], bh);
                mma16816(acc[mt][nt], ah[mt], bl);
            }
        }
    }

    __syncthreads();   // att2/dS/bS ready; also before Cs reuse
    // ---- store acc to smem C ----
    #pragma unroll
    for (int mt = 0; mt < 2; mt++) {
        int rbase = wm*32 + mt*16 + g;
        #pragma unroll
        for (int nt = 0; nt < 8; nt++) {
            int cbase = wn*64 + nt*8 + tg*2;
            float2 v0; v0.x = acc[mt][nt][0]; v0.y = acc[mt][nt][1];
            float2 v1; v1.x = acc[mt][nt][2]; v1.y = acc[mt][nt][3];
            *(float2*)(Cs + rbase*CSTRIDE + cbase)      = v0;
            *(float2*)(Cs + (rbase+8)*CSTRIDE + cbase)  = v1;
        }
    }
    __syncthreads();

    // ---- output-space joint mix + bias + H store + BN stats ----
    {
        int s = tid >> 6;              // sample 0..7
        int c = (tid & 63) * 2;        // channel pair
        float a0[16], a1[16];
        float b0 = bS[c], b1 = bS[c+1];
        #pragma unroll
        for (int i = 0; i < 16; i++) {
            float2 v = *(const float2*)(Cs + (s*16+i)*CSTRIDE + c);
            float d = dS[i];
            a0[i] = fmaf(d, v.x, b0); a1[i] = fmaf(d, v.y, b1);
        }
        #pragma unroll
        for (int j = 0; j < 16; j++) {
            float2 v = *(const float2*)(Cs + (s*16+j)*CSTRIDE + 128 + c);
            #pragma unroll
            for (int i = 0; i < 16; i++) {
                float a = att2[i*16+j];
                a0[i] = fmaf(a, v.x, a0[i]);
                a1[i] = fmaf(a, v.y, a1[i]);
            }
        }
        float cs0 = 0.f, cs1 = 0.f, cq0 = 0.f, cq1 = 0.f;
        #pragma unroll
        for (int i = 0; i < 16; i++) {
            long row = (long)row0 + s*16 + i;
            float2 o; o.x = a0[i]; o.y = a1[i];
            *(float2*)(H + row*128 + c) = o;
            cs0 += o.x; cs1 += o.y; cq0 += o.x*o.x; cq1 += o.y*o.y;
        }
        atomicAdd(&sSum[c],   cs0); atomicAdd(&sSum[c+1], cs1);
        atomicAdd(&sSq [c],   cq0); atomicAdd(&sSq [c+1], cq1);
    }
    __syncthreads();
    if (tid < 128) {
        atomicAdd(&g_sum  [set*NHID + tid], (double)sSum[tid]);
        atomicAdd(&g_sumsq[set*NHID + tid], (double)sSq[tid]);
    }
}

// ---------------- output semgconv (128 -> 3), hi/lo input ----------------
__global__ void sg_gconv_out(const __nv_bfloat16* __restrict__ Xh, const __nv_bfloat16* __restrict__ Xl,
                             const float* __restrict__ Wout, const float* __restrict__ bout,
                             int finalMode, float* __restrict__ outp, float* __restrict__ merged)
{
    __shared__ float xs[4*16*129];
    __shared__ float Wl[768];
    __shared__ float attL[256];
    __shared__ float h1s[4][16][3];
    __shared__ float bL[3];
    int t  = threadIdx.x;              // 128
    int s0 = blockIdx.x * 4;
    int branch = finalMode ? 4 : (s0 >> 13);

    for (int i = t; i < 768; i += 128) Wl[i] = Wout[branch*768 + i];
    for (int i = t; i < 256; i += 128) attL[i] = g_att[(10+branch)*256 + i];
    if (t < 3) bL[t] = bout[branch*3 + t];
    for (int i = t; i < 4*16*128; i += 128) {
        int s = i >> 11, rem = i & 2047, j = rem >> 7, k = rem & 127;
        long gi = ((long)(s0+s)*16 + j)*128 + k;
        xs[(s*16+j)*129 + k] = __bfloat162float(Xh[gi]) + __bfloat162float(Xl[gi]);
    }
    __syncthreads();

    int si = t >> 4, ji = t & 15;
    float h0[3] = {0.f,0.f,0.f};
    if (t < 64) {
        float h1[3] = {0.f,0.f,0.f};
        const float* xr = xs + (si*16 + ji)*129;
        for (int k = 0; k < 128; k++) {
            float x = xr[k];
            h0[0] += x*Wl[k*3+0]; h0[1] += x*Wl[k*3+1]; h0[2] += x*Wl[k*3+2];
            h1[0] += x*Wl[384+k*3+0]; h1[1] += x*Wl[384+k*3+1]; h1[2] += x*Wl[384+k*3+2];
        }
        h1s[si][ji][0]=h1[0]; h1s[si][ji][1]=h1[1]; h1s[si][ji][2]=h1[2];
    }
    __syncthreads();
    if (t < 64) {
        float dd = attL[ji*17];
        float o[3];
        #pragma unroll
        for (int c = 0; c < 3; c++) o[c] = dd*h0[c] + bL[c];
        #pragma unroll
        for (int j = 0; j < 16; j++) {
            if (j == ji) continue;
            float a = attL[ji*16 + j];
            o[0] += a*h1s[si][j][0]; o[1] += a*h1s[si][j][1]; o[2] += a*h1s[si][j][2];
        }
        if (finalMode) {
            long row = ((long)(s0+si)*16 + ji)*3;
            outp[row+0]=o[0]; outp[row+1]=o[1]; outp[row+2]=o[2];
        } else {
            int loc = (s0+si) & (BB-1);
            long ob = (long)(1+branch)*BB*48 + ((long)loc*16 + ji)*3;
            outp[ob+0]=o[0]; outp[ob+1]=o[1]; outp[ob+2]=o[2];
            long mb = ((long)loc*16 + ji)*12 + branch*3;
            merged[mb+0]=o[0]; merged[mb+1]=o[1]; merged[mb+2]=o[2];
        }
    }
}

// ---------------- host orchestration ----------------
extern "C" void kernel_launch(void* const* d_in, const int* in_sizes, int n_in,
                              void* d_out, int out_size)
{
    const float* x1       = (const float*)d_in[0];
    const float* x2       = (const float*)d_in[1];
    const float* x3       = (const float*)d_in[2];
    const float* x4       = (const float*)d_in[3];
    const float* W_in     = (const float*)d_in[4];
    const float* b_in     = (const float*)d_in[5];
    const float* e_in     = (const float*)d_in[6];
    const float* g_in     = (const float*)d_in[7];
    const float* beta_in  = (const float*)d_in[8];
    const float* W_cat    = (const float*)d_in[9];
    const float* b_cat    = (const float*)d_in[10];
    const float* e_cat    = (const float*)d_in[11];
    const float* g_cat    = (const float*)d_in[12];
    const float* beta_cat = (const float*)d_in[13];
    const float* W_res    = (const float*)d_in[14];
    const float* b_res    = (const float*)d_in[15];
    const float* e_res    = (const float*)d_in[16];
    const float* g_res    = (const float*)d_in[17];
    const float* beta_res = (const float*)d_in[18];
    const float* W_out    = (const float*)d_in[19];
    const float* b_out    = (const float*)d_in[20];
    const float* e_out    = (const float*)d_in[21];
    float* out = (float*)d_out;

    float *Hb, *Mb;
    __nv_bfloat16 *Xh0, *Xl0, *Xh1, *Xl1, *Wb;
    cudaGetSymbolAddress((void**)&Hb,  g_H);
    cudaGetSymbolAddress((void**)&Mb,  g_merged);
    cudaGetSymbolAddress((void**)&Xh0, g_Xh0);
    cudaGetSymbolAddress((void**)&Xl0, g_Xl0);
    cudaGetSymbolAddress((void**)&Xh1, g_Xh1);
    cudaGetSymbolAddress((void**)&Xl1, g_Xl1);
    cudaGetSymbolAddress((void**)&Wb,  g_Wbf);

    cudaFuncSetAttribute(sg_gemm_mma, cudaFuncAttributeMaxDynamicSharedMemorySize, MIX_SMEM);

    sg_prep<<<1,256>>>(e_in, e_cat, e_res, e_out);
    sg_wprep<<<1024,256>>>(W_res);

    const float invN = 1.f / (float)(BB*JJ);

    for (int phase = 0; phase < 2; phase++) {
        int nS    = phase ? BB : NS4;
        int nRows = nS*JJ;
        int nSets = phase ? 1 : 4;
        if (phase == 0)
            sg_gconv_smallk<2><<<nS/8,128>>>(x1,x2,x3,x4, 1, W_in, b_in, 0, Hb);
        else
            sg_gconv_smallk<12><<<nS/8,128>>>(Mb, nullptr, nullptr, nullptr, 0, W_cat, b_cat, 1, Hb);
        sg_bn_finalize<<<nSets,128>>>(invN);
        sg_convert<<<nRows/64,256>>>(Hb, nullptr, nullptr, Xh0, Xl0,
                                     phase ? g_cat : g_in, phase ? beta_cat : beta_in);
        for (int s = 0; s < 8; s++) {
            const __nv_bfloat16* Xhi = (s & 1) ? Xh1 : Xh0;
            const __nv_bfloat16* Xli = (s & 1) ? Xl1 : Xl0;
            sg_gemm_mma<<<nRows/128,512,MIX_SMEM>>>(Xhi, Xli, Wb + (long)s*65536,
                                                    b_res + s*128, 2+s, Hb);
            sg_bn_finalize<<<nSets,128>>>(invN);
            __nv_bfloat16* Xho = (s & 1) ? Xh0 : Xh1;
            __nv_bfloat16* Xlo = (s & 1) ? Xl0 : Xl1;
            const __nv_bfloat16* Rh = (s & 1) ? Xh0 : nullptr;
            const __nv_bfloat16* Rl = (s & 1) ? Xl0 : nullptr;
            sg_convert<<<nRows/64,256>>>(Hb, Rh, Rl, Xho, Xlo,
                                         g_res + s*128, beta_res + s*128);
        }
        sg_gconv_out<<<nS/4,128>>>(Xh0, Xl0, W_out, b_out, phase, out, phase ? nullptr : Mb);
    }
}

// round 5
// speedup vs baseline: 2.4265x; 1.6779x over previous
#include <cuda_runtime.h>
#include <cuda_bf16.h>
#include <cstdint>

#define BB   8192
#define JJ   16
#define NHID 128
#define NS4  (4*BB)
#define NRMAX (NS4*JJ)              // 524288 rows
#define EPSB 1e-5f
#define CSTRIDE 260

// smem staging layout (bytes), 272B padded rows (conflict-free for LDSM)
#define ROWP      272
#define OFF_AH    0
#define OFF_AL    (128*ROWP)           // 34816
#define OFF_WH    (2*128*ROWP)         // 69632
#define OFF_WL    (2*128*ROWP + 256*ROWP)
#define GEMM_SMEM (2*128*ROWP + 2*256*ROWP)   // 208896

// ---------------- persistent scratch ----------------
__device__ float         g_H  [NRMAX*NHID];    // pre-BN gconv output (fp32)
__device__ __nv_bfloat16 g_Xh0[NRMAX*NHID];
__device__ __nv_bfloat16 g_Xl0[NRMAX*NHID];
__device__ __nv_bfloat16 g_Xh1[NRMAX*NHID];
__device__ __nv_bfloat16 g_Xl1[NRMAX*NHID];
__device__ __nv_bfloat16 g_Wbf[8*2*256*128];   // [stage][hi/lo][n=256][k=128]
__device__ float  g_merged[BB*JJ*12];
__device__ float  g_att[15*JJ*JJ];
__device__ double g_sum  [4*NHID];
__device__ double g_sumsq[4*NHID];
__device__ float  g_mu  [4*NHID];
__device__ float  g_istd[4*NHID];

__constant__ unsigned short c_mask[16] = {
 0x0093,0x0007,0x000E,0x000C,0x0031,0x0070,0x0060,0x0181,
 0x4B80,0x0700,0x0600,0x1900,0x3800,0x3000,0xC100,0xC000};

// ---------------- PTX helpers ----------------
__device__ __forceinline__ uint32_t smem_u32(const void* p) {
    uint32_t a;
    asm("{ .reg .u64 t; cvta.to.shared.u64 t, %1; cvt.u32.u64 %0, t; }" : "=r"(a) : "l"(p));
    return a;
}
__device__ __forceinline__ void mma16816(float* c, const uint32_t* a, const uint32_t* b) {
    asm volatile("mma.sync.aligned.m16n8k16.row.col.f32.bf16.bf16.f32 "
        "{%0,%1,%2,%3}, {%4,%5,%6,%7}, {%8,%9}, {%0,%1,%2,%3};"
        : "+f"(c[0]), "+f"(c[1]), "+f"(c[2]), "+f"(c[3])
        : "r"(a[0]), "r"(a[1]), "r"(a[2]), "r"(a[3]), "r"(b[0]), "r"(b[1]));
}
__device__ __forceinline__ void ldsm4(uint32_t* r, uint32_t addr) {
    asm volatile("ldmatrix.sync.aligned.m8n8.x4.shared.b16 {%0,%1,%2,%3}, [%4];"
        : "=r"(r[0]), "=r"(r[1]), "=r"(r[2]), "=r"(r[3]) : "r"(addr));
}

// ---------------- prep: masked softmax for all 15 attention matrices ----------------
__global__ void sg_prep(const float* __restrict__ e_in, const float* __restrict__ e_cat,
                        const float* __restrict__ e_res, const float* __restrict__ e_out)
{
    int t = threadIdx.x;
    for (int i = t; i < 4*NHID; i += 256) { g_sum[i] = 0.0; g_sumsq[i] = 0.0; }
    if (t < 240) {
        int slot = t >> 4, i = t & 15;
        const float* e;
        if (slot == 0)      e = e_in;
        else if (slot == 1) e = e_cat;
        else if (slot < 10) e = e_res + (slot-2)*256;
        else                e = e_out + (slot-10)*256;
        unsigned m = c_mask[i];
        float mx = -1e30f;
        for (int j = 0; j < 16; j++) if ((m>>j)&1) mx = fmaxf(mx, e[i*16+j]);
        float v[16]; float s = 0.f;
        for (int j = 0; j < 16; j++) {
            float x = ((m>>j)&1) ? expf(e[i*16+j]-mx) : 0.f;
            v[j] = x; s += x;
        }
        float inv = 1.f/s;
        for (int j = 0; j < 16; j++) g_att[slot*256 + i*16 + j] = v[j]*inv;
    }
}

// ---------------- weight bf16 hi/lo split: g_Wbf[stage][hi/lo][n][k] ----------------
__global__ void sg_wprep(const float* __restrict__ W_res)
{
    int idx = blockIdx.x*256 + threadIdx.x;     // < 262144
    int s = idx >> 15;
    int part = (idx >> 14) & 1;
    int k = (idx >> 7) & 127;
    int c = idx & 127;
    float w = W_res[(((s*2 + part)*128) + k)*128 + c];
    __nv_bfloat16 hi = __float2bfloat16(w);
    __nv_bfloat16 lo = __float2bfloat16(w - __bfloat162float(hi));
    int n = part*128 + c;
    g_Wbf[((long)(s*2+0)*256 + n)*128 + k] = hi;
    g_Wbf[((long)(s*2+1)*256 + n)*128 + k] = lo;
}

// ---------------- small-K input gconv (K=2 / K=12), input-space mixing ----------------
template<int KIN>
__global__ void sg_gconv_smallk(const float* __restrict__ x0, const float* __restrict__ x1,
                                const float* __restrict__ x2, const float* __restrict__ x3,
                                int fourway, const float* __restrict__ W,
                                const float* __restrict__ bias, int attSlot,
                                float* __restrict__ H)
{
    __shared__ float xs [8][16][KIN];
    __shared__ float y0s[8][16][KIN];
    __shared__ float y1s[8][16][KIN];
    __shared__ float Ws[2*KIN*NHID];
    __shared__ float attS[256];
    int t  = threadIdx.x;              // 128
    int s0 = blockIdx.x * 8;
    int set = blockIdx.x >> 10;

    for (int i = t; i < 2*KIN*NHID; i += 128) Ws[i] = W[i];
    for (int i = t; i < 256; i += 128) attS[i] = g_att[attSlot*256 + i];

    const int total = 8*16*KIN;
    for (int i = t; i < total; i += 128) {
        int s = i/(16*KIN); int rem = i - s*16*KIN; int j = rem/KIN; int k = rem - j*KIN;
        int gs = s0 + s;
        const float* xp; int loc;
        if (fourway) {
            int br = gs >> 13; loc = gs & (BB-1);
            xp = (br==0)?x0:(br==1)?x1:(br==2)?x2:x3;
        } else { xp = x0; loc = gs; }
        xs[s][j][k] = xp[(loc*16 + j)*KIN + k];
    }
    __syncthreads();
    for (int i = t; i < total; i += 128) {
        int s = i/(16*KIN); int rem = i - s*16*KIN; int ji = rem/KIN; int k = rem - ji*KIN;
        float a1 = 0.f;
        #pragma unroll
        for (int j = 0; j < 16; j++) a1 += attS[ji*16+j]*xs[s][j][k];
        a1 -= attS[ji*17]*xs[s][ji][k];
        y0s[s][ji][k] = attS[ji*17]*xs[s][ji][k];
        y1s[s][ji][k] = a1;
    }
    __syncthreads();
    int c = t;
    float w0[KIN], w1[KIN];
    #pragma unroll
    for (int k = 0; k < KIN; k++) { w0[k] = Ws[k*NHID+c]; w1[k] = Ws[(KIN+k)*NHID+c]; }
    float bb = bias[c];
    float bsum = 0.f, bsq = 0.f;
    for (int s = 0; s < 8; s++)
        for (int ji = 0; ji < 16; ji++) {
            float h = bb;
            #pragma unroll
            for (int k = 0; k < KIN; k++) h += y0s[s][ji][k]*w0[k] + y1s[s][ji][k]*w1[k];
            H[((long)(s0+s)*16 + ji)*NHID + c] = h;
            bsum += h; bsq += h*h;
        }
    atomicAdd(&g_sum  [set*NHID + c], (double)bsum);
    atomicAdd(&g_sumsq[set*NHID + c], (double)bsq);
}

// ---------------- BN stat finalize ----------------
__global__ void sg_bn_finalize(float invN)
{
    int idx = blockIdx.x*NHID + threadIdx.x;
    double s = g_sum[idx], q = g_sumsq[idx];
    float mu  = (float)(s*(double)invN);
    float var = (float)(q*(double)invN) - mu*mu;
    g_mu[idx] = mu; g_istd[idx] = rsqrtf(var + EPSB);
    g_sum[idx] = 0.0; g_sumsq[idx] = 0.0;
}

// ---------------- convert: BN + ReLU (+residual), write bf16 hi/lo split -------------
__global__ void sg_convert(const float* __restrict__ H,
                           const __nv_bfloat16* __restrict__ Rh, const __nv_bfloat16* __restrict__ Rl,
                           __nv_bfloat16* __restrict__ Xh, __nv_bfloat16* __restrict__ Xl,
                           const float* __restrict__ gma, const float* __restrict__ bta)
{
    int t = threadIdx.x;               // 256
    long base = (long)blockIdx.x * 8192;   // 64 rows
    int set = blockIdx.x >> 11;
    int c0 = (t*4) & 127;
    float a[4], b[4];
    #pragma unroll
    for (int k = 0; k < 4; k++) {
        float mu = g_mu[set*NHID + c0 + k], is = g_istd[set*NHID + c0 + k];
        float gg = gma[c0+k], bb = bta[c0+k];
        a[k] = is*gg; b[k] = bb - mu*is*gg;
    }
    for (int i = t*4; i < 8192; i += 1024) {
        float4 h = *(const float4*)(H + base + i);
        float v[4];
        v[0] = fmaxf(fmaf(h.x, a[0], b[0]), 0.f);
        v[1] = fmaxf(fmaf(h.y, a[1], b[1]), 0.f);
        v[2] = fmaxf(fmaf(h.z, a[2], b[2]), 0.f);
        v[3] = fmaxf(fmaf(h.w, a[3], b[3]), 0.f);
        if (Rh) {
            __nv_bfloat162 rh0 = *(const __nv_bfloat162*)(Rh + base + i);
            __nv_bfloat162 rh1 = *(const __nv_bfloat162*)(Rh + base + i + 2);
            __nv_bfloat162 rl0 = *(const __nv_bfloat162*)(Rl + base + i);
            __nv_bfloat162 rl1 = *(const __nv_bfloat162*)(Rl + base + i + 2);
            v[0] += __bfloat162float(rh0.x) + __bfloat162float(rl0.x);
            v[1] += __bfloat162float(rh0.y) + __bfloat162float(rl0.y);
            v[2] += __bfloat162float(rh1.x) + __bfloat162float(rl1.x);
            v[3] += __bfloat162float(rh1.y) + __bfloat162float(rl1.y);
        }
        __nv_bfloat16 hh[4], ll[4];
        #pragma unroll
        for (int k = 0; k < 4; k++) {
            hh[k] = __float2bfloat16(v[k]);
            ll[k] = __float2bfloat16(v[k] - __bfloat162float(hh[k]));
        }
        __nv_bfloat162 p0, p1, q0, q1;
        p0.x = hh[0]; p0.y = hh[1]; p1.x = hh[2]; p1.y = hh[3];
        q0.x = ll[0]; q0.y = ll[1]; q1.x = ll[2]; q1.y = ll[3];
        *(__nv_bfloat162*)(Xh + base + i)     = p0;
        *(__nv_bfloat162*)(Xh + base + i + 2) = p1;
        *(__nv_bfloat162*)(Xl + base + i)     = q0;
        *(__nv_bfloat162*)(Xl + base + i + 2) = q1;
    }
}

// ---------------- HMMA gemm, smem-staged + ldmatrix -----------------------------------
// C[128x256] = X @ [W0|W1]^T (bf16 hi/lo, 3 passes, fp32 acc)
// Epilogue: H = D*C0 + M1*C1 + bias (output-space joint mix) + BN stats.
__global__ __launch_bounds__(512) void sg_gemm_mma(
    const __nv_bfloat16* __restrict__ Xh, const __nv_bfloat16* __restrict__ Xl,
    const __nv_bfloat16* __restrict__ Wbf, const float* __restrict__ bias,
    int attSlot, float* __restrict__ H)
{
    extern __shared__ char dsm[];      // staging (208896 B), reused as C[128][CSTRIDE]
    __shared__ float att2[256];
    __shared__ float dS[16];
    __shared__ float bS[128];
    __shared__ float sSum[128], sSq[128];

    int tid = threadIdx.x, wid = tid >> 5, lane = tid & 31;
    int row0 = blockIdx.x * 128;
    int set  = blockIdx.x >> 10;
    int wm = wid >> 2, wn = wid & 3;   // 4x4 warp grid, warp tile 32(M) x 64(N)

    if (tid < 128) { bS[tid] = bias[tid]; sSum[tid] = 0.f; sSq[tid] = 0.f; }
    if (tid < 256) {
        float av = g_att[attSlot*256 + tid];
        int i = tid >> 4, j = tid & 15;
        att2[tid] = (i == j) ? 0.f : av;
        if (i == j) dS[i] = av;
    }

    // ---- stage A (128 rows) hi/lo and W (256 rows) hi/lo into padded smem ----
    {
        const uint4* gAh = (const uint4*)(Xh + (long)row0*128);
        const uint4* gAl = (const uint4*)(Xl + (long)row0*128);
        for (int i = tid; i < 2048; i += 512) {        // 128 rows x 16 uint4
            int r = i >> 4, q = i & 15;
            *(uint4*)(dsm + OFF_AH + r*ROWP + q*16) = gAh[i];
            *(uint4*)(dsm + OFF_AL + r*ROWP + q*16) = gAl[i];
        }
        const uint4* gWh = (const uint4*)(Wbf);
        const uint4* gWl = (const uint4*)(Wbf + 256*128);
        for (int i = tid; i < 4096; i += 512) {        // 256 rows x 16 uint4
            int r = i >> 4, q = i & 15;
            *(uint4*)(dsm + OFF_WH + r*ROWP + q*16) = gWh[i];
            *(uint4*)(dsm + OFF_WL + r*ROWP + q*16) = gWl[i];
        }
    }
    __syncthreads();

    uint32_t sbase = smem_u32(dsm);
    // ldmatrix lane addresses
    int sub = lane >> 3, lr = lane & 7;
    // A: matrices {m-lo,k-lo},{m-hi,k-lo},{m-lo,k-hi},{m-hi,k-hi}
    int arow = wm*32 + (sub & 1)*8 + lr;
    uint32_t aAddrH = sbase + OFF_AH + arow*ROWP + (sub >> 1)*16;
    uint32_t aAddrL = sbase + OFF_AL + arow*ROWP + (sub >> 1)*16;
    // B: matrices {n-lo,k-lo},{n-lo,k-hi},{n-hi,k-lo},{n-hi,k-hi}
    int brow = wn*64 + ((lane >> 4) & 1)*8 + lr;
    int bkh  = (lane >> 3) & 1;
    uint32_t bAddrH = sbase + OFF_WH + brow*ROWP + bkh*16;
    uint32_t bAddrL = sbase + OFF_WL + brow*ROWP + bkh*16;

    float acc[2][8][4];
    #pragma unroll
    for (int mt = 0; mt < 2; mt++)
        #pragma unroll
        for (int nt = 0; nt < 8; nt++)
            #pragma unroll
            for (int q = 0; q < 4; q++) acc[mt][nt][q] = 0.f;

    #pragma unroll
    for (int ks = 0; ks < 8; ks++) {
        uint32_t ah[2][4], al[2][4];
        ldsm4(ah[0], aAddrH + ks*32);
        ldsm4(ah[1], aAddrH + ks*32 + 16*ROWP);
        ldsm4(al[0], aAddrL + ks*32);
        ldsm4(al[1], aAddrL + ks*32 + 16*ROWP);
        #pragma unroll
        for (int p = 0; p < 4; p++) {
            uint32_t bh[4], bl[4];
            ldsm4(bh, bAddrH + ks*32 + p*16*ROWP);
            ldsm4(bl, bAddrL + ks*32 + p*16*ROWP);
            #pragma unroll
            for (int half = 0; half < 2; half++) {
                int nt = p*2 + half;
                #pragma unroll
                for (int mt = 0; mt < 2; mt++) {
                    mma16816(acc[mt][nt], ah[mt], bh + half*2);
                    mma16816(acc[mt][nt], al[mt], bh + half*2);
                    mma16816(acc[mt][nt], ah[mt], bl + half*2);
                }
            }
        }
    }
    __syncthreads();   // staging consumed; reuse smem for C

    // ---- store acc to smem C ----
    float* Cs = (float*)dsm;
    {
        int g = lane >> 2, tg = lane & 3;
        #pragma unroll
        for (int mt = 0; mt < 2; mt++) {
            int rbase = wm*32 + mt*16 + g;
            #pragma unroll
            for (int nt = 0; nt < 8; nt++) {
                int cbase = wn*64 + nt*8 + tg*2;
                float2 v0; v0.x = acc[mt][nt][0]; v0.y = acc[mt][nt][1];
                float2 v1; v1.x = acc[mt][nt][2]; v1.y = acc[mt][nt][3];
                *(float2*)(Cs + rbase*CSTRIDE + cbase)      = v0;
                *(float2*)(Cs + (rbase+8)*CSTRIDE + cbase)  = v1;
            }
        }
    }
    __syncthreads();

    // ---- output-space joint mix + bias + H store + BN stats ----
    {
        int s = tid >> 6;              // sample 0..7
        int c = (tid & 63) * 2;        // channel pair
        float a0[16], a1[16];
        float b0 = bS[c], b1 = bS[c+1];
        #pragma unroll
        for (int i = 0; i < 16; i++) {
            float2 v = *(const float2*)(Cs + (s*16+i)*CSTRIDE + c);
            float d = dS[i];
            a0[i] = fmaf(d, v.x, b0); a1[i] = fmaf(d, v.y, b1);
        }
        #pragma unroll
        for (int j = 0; j < 16; j++) {
            float2 v = *(const float2*)(Cs + (s*16+j)*CSTRIDE + 128 + c);
            #pragma unroll
            for (int i = 0; i < 16; i++) {
                float a = att2[i*16+j];
                a0[i] = fmaf(a, v.x, a0[i]);
                a1[i] = fmaf(a, v.y, a1[i]);
            }
        }
        float cs0 = 0.f, cs1 = 0.f, cq0 = 0.f, cq1 = 0.f;
        #pragma unroll
        for (int i = 0; i < 16; i++) {
            long row = (long)row0 + s*16 + i;
            float2 o; o.x = a0[i]; o.y = a1[i];
            *(float2*)(H + row*128 + c) = o;
            cs0 += o.x; cs1 += o.y; cq0 += o.x*o.x; cq1 += o.y*o.y;
        }
        atomicAdd(&sSum[c],   cs0); atomicAdd(&sSum[c+1], cs1);
        atomicAdd(&sSq [c],   cq0); atomicAdd(&sSq [c+1], cq1);
    }
    __syncthreads();
    if (tid < 128) {
        atomicAdd(&g_sum  [set*NHID + tid], (double)sSum[tid]);
        atomicAdd(&g_sumsq[set*NHID + tid], (double)sSq[tid]);
    }
}

// ---------------- output semgconv (128 -> 3), hi/lo input ----------------
__global__ void sg_gconv_out(const __nv_bfloat16* __restrict__ Xh, const __nv_bfloat16* __restrict__ Xl,
                             const float* __restrict__ Wout, const float* __restrict__ bout,
                             int finalMode, float* __restrict__ outp, float* __restrict__ merged)
{
    __shared__ float xs[4*16*129];
    __shared__ float Wl[768];
    __shared__ float attL[256];
    __shared__ float h1s[4][16][3];
    __shared__ float bL[3];
    int t  = threadIdx.x;              // 128
    int s0 = blockIdx.x * 4;
    int branch = finalMode ? 4 : (s0 >> 13);

    for (int i = t; i < 768; i += 128) Wl[i] = Wout[branch*768 + i];
    for (int i = t; i < 256; i += 128) attL[i] = g_att[(10+branch)*256 + i];
    if (t < 3) bL[t] = bout[branch*3 + t];
    for (int i = t; i < 4*16*128; i += 128) {
        int s = i >> 11, rem = i & 2047, j = rem >> 7, k = rem & 127;
        long gi = ((long)(s0+s)*16 + j)*128 + k;
        xs[(s*16+j)*129 + k] = __bfloat162float(Xh[gi]) + __bfloat162float(Xl[gi]);
    }
    __syncthreads();

    int si = t >> 4, ji = t & 15;
    float h0[3] = {0.f,0.f,0.f};
    if (t < 64) {
        float h1[3] = {0.f,0.f,0.f};
        const float* xr = xs + (si*16 + ji)*129;
        for (int k = 0; k < 128; k++) {
            float x = xr[k];
            h0[0] += x*Wl[k*3+0]; h0[1] += x*Wl[k*3+1]; h0[2] += x*Wl[k*3+2];
            h1[0] += x*Wl[384+k*3+0]; h1[1] += x*Wl[384+k*3+1]; h1[2] += x*Wl[384+k*3+2];
        }
        h1s[si][ji][0]=h1[0]; h1s[si][ji][1]=h1[1]; h1s[si][ji][2]=h1[2];
    }
    __syncthreads();
    if (t < 64) {
        float dd = attL[ji*17];
        float o[3];
        #pragma unroll
        for (int c = 0; c < 3; c++) o[c] = dd*h0[c] + bL[c];
        #pragma unroll
        for (int j = 0; j < 16; j++) {
            if (j == ji) continue;
            float a = attL[ji*16 + j];
            o[0] += a*h1s[si][j][0]; o[1] += a*h1s[si][j][1]; o[2] += a*h1s[si][j][2];
        }
        if (finalMode) {
            long row = ((long)(s0+si)*16 + ji)*3;
            outp[row+0]=o[0]; outp[row+1]=o[1]; outp[row+2]=o[2];
        } else {
            int loc = (s0+si) & (BB-1);
            long ob = (long)(1+branch)*BB*48 + ((long)loc*16 + ji)*3;
            outp[ob+0]=o[0]; outp[ob+1]=o[1]; outp[ob+2]=o[2];
            long mb = ((long)loc*16 + ji)*12 + branch*3;
            merged[mb+0]=o[0]; merged[mb+1]=o[1]; merged[mb+2]=o[2];
        }
    }
}

// ---------------- host orchestration ----------------
extern "C" void kernel_launch(void* const* d_in, const int* in_sizes, int n_in,
                              void* d_out, int out_size)
{
    const float* x1       = (const float*)d_in[0];
    const float* x2       = (const float*)d_in[1];
    const float* x3       = (const float*)d_in[2];
    const float* x4       = (const float*)d_in[3];
    const float* W_in     = (const float*)d_in[4];
    const float* b_in     = (const float*)d_in[5];
    const float* e_in     = (const float*)d_in[6];
    const float* g_in     = (const float*)d_in[7];
    const float* beta_in  = (const float*)d_in[8];
    const float* W_cat    = (const float*)d_in[9];
    const float* b_cat    = (const float*)d_in[10];
    const float* e_cat    = (const float*)d_in[11];
    const float* g_cat    = (const float*)d_in[12];
    const float* beta_cat = (const float*)d_in[13];
    const float* W_res    = (const float*)d_in[14];
    const float* b_res    = (const float*)d_in[15];
    const float* e_res    = (const float*)d_in[16];
    const float* g_res    = (const float*)d_in[17];
    const float* beta_res = (const float*)d_in[18];
    const float* W_out    = (const float*)d_in[19];
    const float* b_out    = (const float*)d_in[20];
    const float* e_out    = (const float*)d_in[21];
    float* out = (float*)d_out;

    float *Hb, *Mb;
    __nv_bfloat16 *Xh0, *Xl0, *Xh1, *Xl1, *Wb;
    cudaGetSymbolAddress((void**)&Hb,  g_H);
    cudaGetSymbolAddress((void**)&Mb,  g_merged);
    cudaGetSymbolAddress((void**)&Xh0, g_Xh0);
    cudaGetSymbolAddress((void**)&Xl0, g_Xl0);
    cudaGetSymbolAddress((void**)&Xh1, g_Xh1);
    cudaGetSymbolAddress((void**)&Xl1, g_Xl1);
    cudaGetSymbolAddress((void**)&Wb,  g_Wbf);

    cudaFuncSetAttribute(sg_gemm_mma, cudaFuncAttributeMaxDynamicSharedMemorySize, GEMM_SMEM);

    sg_prep<<<1,256>>>(e_in, e_cat, e_res, e_out);
    sg_wprep<<<1024,256>>>(W_res);

    const float invN = 1.f / (float)(BB*JJ);

    for (int phase = 0; phase < 2; phase++) {
        int nS    = phase ? BB : NS4;
        int nRows = nS*JJ;
        int nSets = phase ? 1 : 4;
        if (phase == 0)
            sg_gconv_smallk<2><<<nS/8,128>>>(x1,x2,x3,x4, 1, W_in, b_in, 0, Hb);
        else
            sg_gconv_smallk<12><<<nS/8,128>>>(Mb, nullptr, nullptr, nullptr, 0, W_cat, b_cat, 1, Hb);
        sg_bn_finalize<<<nSets,128>>>(invN);
        sg_convert<<<nRows/64,256>>>(Hb, nullptr, nullptr, Xh0, Xl0,
                                     phase ? g_cat : g_in, phase ? beta_cat : beta_in);
        for (int s = 0; s < 8; s++) {
            const __nv_bfloat16* Xhi = (s & 1) ? Xh1 : Xh0;
            const __nv_bfloat16* Xli = (s & 1) ? Xl1 : Xl0;
            sg_gemm_mma<<<nRows/128,512,GEMM_SMEM>>>(Xhi, Xli, Wb + (long)s*65536,
                                                     b_res + s*128, 2+s, Hb);
            sg_bn_finalize<<<nSets,128>>>(invN);
            __nv_bfloat16* Xho = (s & 1) ? Xh0 : Xh1;
            __nv_bfloat16* Xlo = (s & 1) ? Xl0 : Xl1;
            const __nv_bfloat16* Rh = (s & 1) ? Xh0 : nullptr;
            const __nv_bfloat16* Rl = (s & 1) ? Xl0 : nullptr;
            sg_convert<<<nRows/64,256>>>(Hb, Rh, Rl, Xho, Xlo,
                                         g_res + s*128, beta_res + s*128);
        }
        sg_gconv_out<<<nS/4,128>>>(Xh0, Xl0, W_out, b_out, phase, out, phase ? nullptr : Mb);
    }
}